// round 4
// baseline (speedup 1.0000x reference)
#include <cuda_runtime.h>
#include <cuda_fp16.h>
#include <cstdint>

#define NB      4
#define NNODES  50000
#define DIN     128
#define DOUT    64
#define NEDGES  800000
#define MTOTAL  (NB * NNODES)

// ---------------- device scratch ----------------
// pre layout: [node][dout][batch] fp16  -> 16B per (node, col-pair) per lane
__device__ __half g_preh[NNODES * DOUT * NB];
__device__ int   g_counts[NNODES];
__device__ int   g_offs[NNODES + 1];
__device__ int   g_cursor[NNODES];
__device__ int2  g_edge[NEDGES];     // {col, float_as_int(val)}

// ---------------- packed f32x2 helpers ----------------
__device__ __forceinline__ void ffma2(unsigned long long& d,
                                      unsigned long long a,
                                      unsigned long long b) {
    asm("fma.rn.f32x2 %0, %1, %2, %0;" : "+l"(d) : "l"(a), "l"(b));
}
__device__ __forceinline__ unsigned long long pack2(float x) {
    unsigned long long r;
    asm("mov.b64 %0, {%1, %1};" : "=l"(r) : "f"(x));
    return r;
}
__device__ __forceinline__ float2 unpack2(unsigned long long a) {
    float lo, hi;
    asm("mov.b64 {%0, %1}, %2;" : "=f"(lo), "=f"(hi) : "l"(a));
    return make_float2(lo, hi);
}
__device__ __forceinline__ unsigned int h2u(__half2 h) {
    return *reinterpret_cast<unsigned int*>(&h);
}

// ---------------- CSR build ----------------
__global__ void zero_counts_kernel() {
    int i = blockIdx.x * blockDim.x + threadIdx.x;
    if (i < NNODES) g_counts[i] = 0;
}

__global__ void hist_kernel(const int* __restrict__ erows) {
    int e = blockIdx.x * blockDim.x + threadIdx.x;
    if (e < NEDGES) atomicAdd(&g_counts[erows[e]], 1);
}

// single-block scan: shuffle-based, 4 elems/thread, 4096 per chunk
__global__ void scan_kernel() {
    __shared__ int wsum[32];
    __shared__ int s_carry;
    __shared__ int s_total;
    int tid = threadIdx.x, lane = tid & 31, wid = tid >> 5;
    if (tid == 0) s_carry = 0;
    __syncthreads();

    for (int base = 0; base < NNODES; base += 4096) {
        int i0 = base + tid * 4;
        int v0 = (i0 + 0 < NNODES) ? g_counts[i0 + 0] : 0;
        int v1 = (i0 + 1 < NNODES) ? g_counts[i0 + 1] : 0;
        int v2 = (i0 + 2 < NNODES) ? g_counts[i0 + 2] : 0;
        int v3 = (i0 + 3 < NNODES) ? g_counts[i0 + 3] : 0;
        int c0 = v0, c1 = c0 + v1, c2 = c1 + v2, c3 = c2 + v3;

        int s = c3;
        #pragma unroll
        for (int off = 1; off < 32; off <<= 1) {
            int n = __shfl_up_sync(0xffffffffu, s, off);
            if (lane >= off) s += n;
        }
        if (lane == 31) wsum[wid] = s;
        __syncthreads();
        if (wid == 0) {
            int t = wsum[lane];
            #pragma unroll
            for (int off = 1; off < 32; off <<= 1) {
                int n = __shfl_up_sync(0xffffffffu, t, off);
                if (lane >= off) t += n;
            }
            wsum[lane] = t;
            if (lane == 31) s_total = t;
        }
        __syncthreads();

        int excl = s_carry + (wid > 0 ? wsum[wid - 1] : 0) + (s - c3);
        if (i0 + 0 < NNODES) { g_offs[i0 + 1] = excl + c0; g_cursor[i0 + 0] = excl; }
        if (i0 + 1 < NNODES) { g_offs[i0 + 2] = excl + c1; g_cursor[i0 + 1] = excl + c0; }
        if (i0 + 2 < NNODES) { g_offs[i0 + 3] = excl + c2; g_cursor[i0 + 2] = excl + c1; }
        if (i0 + 3 < NNODES) { g_offs[i0 + 4] = excl + c3; g_cursor[i0 + 3] = excl + c2; }
        __syncthreads();
        if (tid == 0) s_carry += s_total;
        __syncthreads();
    }
    if (threadIdx.x == 0) g_offs[0] = 0;
}

// scatter: 4 independent edges per thread (MLP for atomic-return latency),
// packed 8B store
__global__ void scatter_kernel(const int* __restrict__ erows,
                               const int* __restrict__ ecols,
                               const float* __restrict__ evals) {
    int base = blockIdx.x * 1024 + threadIdx.x;
    #pragma unroll
    for (int i = 0; i < 4; i++) {
        int e = base + i * 256;
        if (e < NEDGES) {
            int r = erows[e];
            int pos = atomicAdd(&g_cursor[r], 1);
            g_edge[pos] = make_int2(ecols[e], __float_as_int(evals[e]));
        }
    }
}

// ---------------- GEMM: preh[n][d][b] = fp16( x[b][n][:] @ W[:,d] ) ----------------
// block: 32 nodes x 64 cols x 4 batches; thread: 1 node x 8 cols x 4 batches
__global__ void gemm_kernel(const float* __restrict__ x,
                            const float* __restrict__ w) {
    __shared__ float xs[4][32][36];   // [batch][node][k], padded
    __shared__ float ws[32][64];      // [k][col]
    int t  = threadIdx.x;
    int tx = t & 7;           // col oct: cols tx*8 .. tx*8+7
    int ty = t >> 3;          // node 0..31
    int nb = blockIdx.x * 32;

    unsigned long long acc[4][4] = {};   // [batch][col-pair]

    // x-load mapping: 8 k-quads x 32 nodes
    int kq = t & 7;
    int nl = t >> 3;
    int ng = nb + nl;
    int ngc = (ng < NNODES) ? ng : (NNODES - 1);   // clamp OOB reads

    for (int kc = 0; kc < DIN; kc += 32) {
        #pragma unroll
        for (int b = 0; b < 4; b++) {
            float4 v = *reinterpret_cast<const float4*>(
                x + ((size_t)b * NNODES + ngc) * DIN + kc + kq * 4);
            *reinterpret_cast<float4*>(&xs[b][nl][kq * 4]) = v;
        }
        #pragma unroll
        for (int i2 = 0; i2 < 2; i2++) {
            int idx = t + i2 * 256;
            int kr = idx >> 4;
            int cq = idx & 15;
            float4 v = *reinterpret_cast<const float4*>(
                w + (size_t)(kc + kr) * DOUT + cq * 4);
            *reinterpret_cast<float4*>(&ws[kr][cq * 4]) = v;
        }
        __syncthreads();
        #pragma unroll
        for (int k = 0; k < 32; k++) {
            ulonglong2 w0 = *reinterpret_cast<const ulonglong2*>(&ws[k][tx * 8]);
            ulonglong2 w1 = *reinterpret_cast<const ulonglong2*>(&ws[k][tx * 8 + 4]);
            #pragma unroll
            for (int b = 0; b < 4; b++) {
                unsigned long long xp = pack2(xs[b][ty][k]);
                ffma2(acc[b][0], xp, w0.x);
                ffma2(acc[b][1], xp, w0.y);
                ffma2(acc[b][2], xp, w1.x);
                ffma2(acc[b][3], xp, w1.y);
            }
        }
        __syncthreads();
    }

    if (nb + ty < NNODES) {
        __half* basep = g_preh + ((size_t)(nb + ty) * DOUT + tx * 8) * NB;
        #pragma unroll
        for (int c4 = 0; c4 < 4; c4++) {
            float2 e = unpack2(acc[0][c4]);
            float2 f = unpack2(acc[1][c4]);
            float2 g = unpack2(acc[2][c4]);
            float2 h = unpack2(acc[3][c4]);
            // col d0 = tx*8 + c4*2 : batches (e.x, f.x, g.x, h.x)
            // col d1 = d0 + 1      : batches (e.y, f.y, g.y, h.y)
            uint4 pk;
            pk.x = h2u(__floats2half2_rn(e.x, f.x));
            pk.y = h2u(__floats2half2_rn(g.x, h.x));
            pk.z = h2u(__floats2half2_rn(e.y, f.y));
            pk.w = h2u(__floats2half2_rn(g.y, h.y));
            *reinterpret_cast<uint4*>(basep + c4 * 8) = pk;   // 16B, covers 2 cols x 4 batches
        }
    }
}

// ---------------- aggregation: warp per destination row ----------------
// per edge per lane: ONE 16B coalesced load = 2 cols x 4 batches
__device__ __forceinline__ void accum_q(uint4 q, float v,
                                        float2& a0, float2& a1,
                                        float2& a2, float2& a3) {
    float2 f;
    f = __half22float2(*reinterpret_cast<__half2*>(&q.x));
    a0.x += v * f.x; a1.x += v * f.y;
    f = __half22float2(*reinterpret_cast<__half2*>(&q.y));
    a2.x += v * f.x; a3.x += v * f.y;
    f = __half22float2(*reinterpret_cast<__half2*>(&q.z));
    a0.y += v * f.x; a1.y += v * f.y;
    f = __half22float2(*reinterpret_cast<__half2*>(&q.w));
    a2.y += v * f.x; a3.y += v * f.y;
}

__global__ void aggregate_kernel(float* __restrict__ out) {
    int gwarp = (blockIdx.x * blockDim.x + threadIdx.x) >> 5;
    int lane  = threadIdx.x & 31;
    if (gwarp >= NNODES) return;

    int start = g_offs[gwarp];
    int end   = g_offs[gwarp + 1];

    float2 a0 = make_float2(0.f, 0.f), a1 = a0, a2 = a0, a3 = a0;
    const uint4* p4 = reinterpret_cast<const uint4*>(g_preh);   // 16B units; node stride = 32

    int i = start;
    for (; i + 1 < end; i += 2) {
        int2 e0 = g_edge[i];
        int2 e1 = g_edge[i + 1];
        uint4 q0 = p4[(size_t)e0.x * 32 + lane];
        uint4 q1 = p4[(size_t)e1.x * 32 + lane];
        accum_q(q0, __int_as_float(e0.y), a0, a1, a2, a3);
        accum_q(q1, __int_as_float(e1.y), a0, a1, a2, a3);
    }
    if (i < end) {
        int2 e0 = g_edge[i];
        uint4 q0 = p4[(size_t)e0.x * 32 + lane];
        accum_q(q0, __int_as_float(e0.y), a0, a1, a2, a3);
    }

    float2* o2 = reinterpret_cast<float2*>(out);
    const size_t bstride = (size_t)NNODES * (DOUT / 2);
    size_t ob = (size_t)gwarp * (DOUT / 2) + lane;
    o2[ob]               = make_float2(fmaxf(a0.x, 0.f), fmaxf(a0.y, 0.f));
    o2[ob +     bstride] = make_float2(fmaxf(a1.x, 0.f), fmaxf(a1.y, 0.f));
    o2[ob + 2 * bstride] = make_float2(fmaxf(a2.x, 0.f), fmaxf(a2.y, 0.f));
    o2[ob + 3 * bstride] = make_float2(fmaxf(a3.x, 0.f), fmaxf(a3.y, 0.f));
}

// ---------------- launch ----------------
extern "C" void kernel_launch(void* const* d_in, const int* in_sizes, int n_in,
                              void* d_out, int out_size) {
    const float* x     = (const float*)d_in[0];
    const float* w     = (const float*)d_in[1];
    const float* evals = (const float*)d_in[2];
    const int*   erows = (const int*)  d_in[3];
    const int*   ecols = (const int*)  d_in[4];
    float* out = (float*)d_out;

    (void)in_sizes; (void)n_in; (void)out_size;

    zero_counts_kernel<<<(NNODES + 255) / 256, 256>>>();
    hist_kernel<<<NEDGES / 256, 256>>>(erows);
    scan_kernel<<<1, 1024>>>();
    scatter_kernel<<<(NEDGES + 1023) / 1024, 256>>>(erows, ecols, evals);

    gemm_kernel<<<(NNODES + 31) / 32, 256>>>(x, w);

    aggregate_kernel<<<(NNODES * 32 + 255) / 256, 256>>>(out);
}

// round 5
// speedup vs baseline: 1.3674x; 1.3674x over previous
#include <cuda_runtime.h>
#include <cuda_fp16.h>
#include <cstdint>

#define NB      4
#define NNODES  50000
#define DIN     128
#define DOUT    64
#define NEDGES  800000
#define MTOTAL  (NB * NNODES)

// ---------------- device scratch ----------------
// pre layout: [b][node][dout] fp16 (R2-proven layout)
__device__ __half g_preh[MTOTAL * DOUT];
__device__ int   g_counts[NNODES];
__device__ int   g_offs[NNODES + 1];
__device__ int   g_cursor[NNODES];
__device__ int2  g_edge[NEDGES];     // {col, float_as_int(val)}

// ---------------- tf32 helpers ----------------
__device__ __forceinline__ unsigned int f2tf32(float f) {
    unsigned int u;
    asm("cvt.rna.tf32.f32 %0, %1;" : "=r"(u) : "f"(f));
    return u;
}
__device__ __forceinline__ void mma_tf32(float4& d,
                                         unsigned int a0, unsigned int a1,
                                         unsigned int a2, unsigned int a3,
                                         unsigned int b0, unsigned int b1) {
    asm("mma.sync.aligned.m16n8k8.row.col.f32.tf32.tf32.f32 "
        "{%0,%1,%2,%3}, {%4,%5,%6,%7}, {%8,%9}, {%0,%1,%2,%3};"
        : "+f"(d.x), "+f"(d.y), "+f"(d.z), "+f"(d.w)
        : "r"(a0), "r"(a1), "r"(a2), "r"(a3), "r"(b0), "r"(b1));
}

// ---------------- CSR build ----------------
__global__ void zero_counts_kernel() {
    int i = blockIdx.x * blockDim.x + threadIdx.x;
    if (i < NNODES) g_counts[i] = 0;
}

__global__ void hist_kernel(const int* __restrict__ erows) {
    int e = blockIdx.x * blockDim.x + threadIdx.x;
    if (e < NEDGES) atomicAdd(&g_counts[erows[e]], 1);
}

// single-block scan: shuffle-based, 4 elems/thread
__global__ void scan_kernel() {
    __shared__ int wsum[32];
    __shared__ int s_carry;
    __shared__ int s_total;
    int tid = threadIdx.x, lane = tid & 31, wid = tid >> 5;
    if (tid == 0) s_carry = 0;
    __syncthreads();

    for (int base = 0; base < NNODES; base += 4096) {
        int i0 = base + tid * 4;
        int v0 = (i0 + 0 < NNODES) ? g_counts[i0 + 0] : 0;
        int v1 = (i0 + 1 < NNODES) ? g_counts[i0 + 1] : 0;
        int v2 = (i0 + 2 < NNODES) ? g_counts[i0 + 2] : 0;
        int v3 = (i0 + 3 < NNODES) ? g_counts[i0 + 3] : 0;
        int c0 = v0, c1 = c0 + v1, c2 = c1 + v2, c3 = c2 + v3;

        int s = c3;
        #pragma unroll
        for (int off = 1; off < 32; off <<= 1) {
            int n = __shfl_up_sync(0xffffffffu, s, off);
            if (lane >= off) s += n;
        }
        if (lane == 31) wsum[wid] = s;
        __syncthreads();
        if (wid == 0) {
            int t = wsum[lane];
            #pragma unroll
            for (int off = 1; off < 32; off <<= 1) {
                int n = __shfl_up_sync(0xffffffffu, t, off);
                if (lane >= off) t += n;
            }
            wsum[lane] = t;
            if (lane == 31) s_total = t;
        }
        __syncthreads();

        int excl = s_carry + (wid > 0 ? wsum[wid - 1] : 0) + (s - c3);
        if (i0 + 0 < NNODES) { g_offs[i0 + 1] = excl + c0; g_cursor[i0 + 0] = excl; }
        if (i0 + 1 < NNODES) { g_offs[i0 + 2] = excl + c1; g_cursor[i0 + 1] = excl + c0; }
        if (i0 + 2 < NNODES) { g_offs[i0 + 3] = excl + c2; g_cursor[i0 + 2] = excl + c1; }
        if (i0 + 3 < NNODES) { g_offs[i0 + 4] = excl + c3; g_cursor[i0 + 3] = excl + c2; }
        __syncthreads();
        if (tid == 0) s_carry += s_total;
        __syncthreads();
    }
    if (threadIdx.x == 0) g_offs[0] = 0;
}

// scatter: 4 independent edges per thread, packed 8B store
__global__ void scatter_kernel(const int* __restrict__ erows,
                               const int* __restrict__ ecols,
                               const float* __restrict__ evals) {
    int base = blockIdx.x * 1024 + threadIdx.x;
    #pragma unroll
    for (int i = 0; i < 4; i++) {
        int e = base + i * 256;
        if (e < NEDGES) {
            int r = erows[e];
            int pos = atomicAdd(&g_cursor[r], 1);
            g_edge[pos] = make_int2(ecols[e], __float_as_int(evals[e]));
        }
    }
}

// ---------------- GEMM: tf32 mma.sync, preh[m][d] = fp16( x[m,:] @ W ) ----------------
// block: 256 threads = 8 warps; warp tile 16(M) x 64(N); block tile 128 x 64.
// W staged in smem pre-arranged in B-fragment order: wsf[kk][j][lane][2reg].
__global__ __launch_bounds__(256) void gemm_kernel(const float* __restrict__ x,
                                                   const float* __restrict__ w) {
    __shared__ unsigned int wsf[16 * 8 * 32 * 2];   // 32 KB
    int t = threadIdx.x, lane = t & 31, wid = t >> 5;

    // fill W fragments: i = ((kk*8 + j)*32 + lane)*2 + reg
    for (int i = t; i < 8192; i += 256) {
        int kk = i >> 9;
        int j  = (i >> 6) & 7;
        int ln = (i >> 1) & 31;
        int rg = i & 1;
        int k  = kk * 8 + (ln & 3) + rg * 4;
        int c  = j * 8 + (ln >> 2);
        wsf[i] = f2tf32(w[k * DOUT + c]);
    }
    __syncthreads();

    size_t m0 = (size_t)blockIdx.x * 128 + wid * 16;
    int g   = lane >> 2;     // groupID (row within fragment)
    int tig = lane & 3;      // thread in group (k / col pair index)

    size_t mr0 = m0 + g;
    size_t mr1 = m0 + g + 8;
    const float* xr0 = x + (mr0 < MTOTAL ? mr0 : (size_t)(MTOTAL - 1)) * DIN;
    const float* xr1 = x + (mr1 < MTOTAL ? mr1 : (size_t)(MTOTAL - 1)) * DIN;

    float4 acc[8] = {};
    const uint2* wsf2 = reinterpret_cast<const uint2*>(wsf);

    #pragma unroll
    for (int kk = 0; kk < 16; kk++) {
        int k0 = kk * 8 + tig;
        unsigned int a0 = f2tf32(xr0[k0]);
        unsigned int a1 = f2tf32(xr1[k0]);
        unsigned int a2 = f2tf32(xr0[k0 + 4]);
        unsigned int a3 = f2tf32(xr1[k0 + 4]);
        #pragma unroll
        for (int j = 0; j < 8; j++) {
            uint2 b = wsf2[(kk * 8 + j) * 32 + lane];
            mma_tf32(acc[j], a0, a1, a2, a3, b.x, b.y);
        }
    }

    bool v0 = mr0 < MTOTAL;
    bool v1 = mr1 < MTOTAL;
    #pragma unroll
    for (int j = 0; j < 8; j++) {
        // c0,c1 -> (row g,   cols j*8 + 2*tig, +1)
        // c2,c3 -> (row g+8, same cols)
        __half2 h0 = __floats2half2_rn(acc[j].x, acc[j].y);
        __half2 h1 = __floats2half2_rn(acc[j].z, acc[j].w);
        if (v0) *reinterpret_cast<__half2*>(g_preh + mr0 * DOUT + j * 8 + tig * 2) = h0;
        if (v1) *reinterpret_cast<__half2*>(g_preh + mr1 * DOUT + j * 8 + tig * 2) = h1;
    }
}

// ---------------- aggregation: warp per destination row (R2-proven form) ----------------
__global__ void aggregate_kernel(float* __restrict__ out) {
    int gwarp = (blockIdx.x * blockDim.x + threadIdx.x) >> 5;
    int lane  = threadIdx.x & 31;
    if (gwarp >= NNODES) return;

    int start = g_offs[gwarp];
    int end   = g_offs[gwarp + 1];

    float2 a0 = make_float2(0.f, 0.f), a1 = a0, a2 = a0, a3 = a0;
    const __half2* p2 = reinterpret_cast<const __half2*>(g_preh);
    const size_t bstride = (size_t)NNODES * (DOUT / 2);

    for (int i = start; i < end; i++) {
        int2 e = g_edge[i];
        float v = __int_as_float(e.y);
        size_t base = (size_t)e.x * (DOUT / 2) + lane;
        float2 f;
        f = __half22float2(p2[base]);               a0.x += v * f.x; a0.y += v * f.y;
        f = __half22float2(p2[base +     bstride]); a1.x += v * f.x; a1.y += v * f.y;
        f = __half22float2(p2[base + 2 * bstride]); a2.x += v * f.x; a2.y += v * f.y;
        f = __half22float2(p2[base + 3 * bstride]); a3.x += v * f.x; a3.y += v * f.y;
    }

    float2* o2 = reinterpret_cast<float2*>(out);
    size_t ob = (size_t)gwarp * (DOUT / 2) + lane;
    o2[ob]               = make_float2(fmaxf(a0.x, 0.f), fmaxf(a0.y, 0.f));
    o2[ob +     bstride] = make_float2(fmaxf(a1.x, 0.f), fmaxf(a1.y, 0.f));
    o2[ob + 2 * bstride] = make_float2(fmaxf(a2.x, 0.f), fmaxf(a2.y, 0.f));
    o2[ob + 3 * bstride] = make_float2(fmaxf(a3.x, 0.f), fmaxf(a3.y, 0.f));
}

// ---------------- launch ----------------
extern "C" void kernel_launch(void* const* d_in, const int* in_sizes, int n_in,
                              void* d_out, int out_size) {
    const float* x     = (const float*)d_in[0];
    const float* w     = (const float*)d_in[1];
    const float* evals = (const float*)d_in[2];
    const int*   erows = (const int*)  d_in[3];
    const int*   ecols = (const int*)  d_in[4];
    float* out = (float*)d_out;

    (void)in_sizes; (void)n_in; (void)out_size;

    zero_counts_kernel<<<(NNODES + 255) / 256, 256>>>();
    hist_kernel<<<NEDGES / 256, 256>>>(erows);
    scan_kernel<<<1, 1024>>>();
    // gemm placed 4th so the ncu capture slot profiles it next round
    gemm_kernel<<<(MTOTAL + 127) / 128, 256>>>(x, w);
    scatter_kernel<<<(NEDGES + 1023) / 1024, 256>>>(erows, ecols, evals);
    aggregate_kernel<<<(NNODES * 32 + 255) / 256, 256>>>(out);
}

// round 6
// speedup vs baseline: 1.4217x; 1.0397x over previous
#include <cuda_runtime.h>
#include <cuda_fp16.h>
#include <cstdint>

#define NB      4
#define NNODES  50000
#define DIN     128
#define DOUT    64
#define NEDGES  800000
#define MTOTAL  (NB * NNODES)

#define XS_STRIDE 36                      // 32 + 4 pad: bank = (4*row + k) % 32
#define GEMM_SMEM (128 * XS_STRIDE * 4 + 16 * 8 * 32 * 2 * 4)   // 18432 + 32768 = 51200 B

// ---------------- device scratch ----------------
// pre layout: [b][node][dout] fp16
__device__ __half g_preh[MTOTAL * DOUT];
__device__ int   g_counts[NNODES];
__device__ int   g_offs[NNODES + 1];
__device__ int   g_cursor[NNODES];
__device__ int2  g_edge[NEDGES];     // {col, float_as_int(val)}

// ---------------- tf32 helpers ----------------
__device__ __forceinline__ unsigned int f2tf32(float f) {
    unsigned int u;
    asm("cvt.rna.tf32.f32 %0, %1;" : "=r"(u) : "f"(f));
    return u;
}
__device__ __forceinline__ void mma_tf32(float4& d,
                                         unsigned int a0, unsigned int a1,
                                         unsigned int a2, unsigned int a3,
                                         unsigned int b0, unsigned int b1) {
    asm("mma.sync.aligned.m16n8k8.row.col.f32.tf32.tf32.f32 "
        "{%0,%1,%2,%3}, {%4,%5,%6,%7}, {%8,%9}, {%0,%1,%2,%3};"
        : "+f"(d.x), "+f"(d.y), "+f"(d.z), "+f"(d.w)
        : "r"(a0), "r"(a1), "r"(a2), "r"(a3), "r"(b0), "r"(b1));
}

// ---------------- CSR build ----------------
__global__ void zero_counts_kernel() {
    int i = blockIdx.x * blockDim.x + threadIdx.x;
    if (i < NNODES) g_counts[i] = 0;
}

__global__ void hist_kernel(const int* __restrict__ erows) {
    int e = blockIdx.x * blockDim.x + threadIdx.x;
    if (e < NEDGES) atomicAdd(&g_counts[erows[e]], 1);
}

// single-block scan: shuffle-based, 4 elems/thread
__global__ void scan_kernel() {
    __shared__ int wsum[32];
    __shared__ int s_carry;
    __shared__ int s_total;
    int tid = threadIdx.x, lane = tid & 31, wid = tid >> 5;
    if (tid == 0) s_carry = 0;
    __syncthreads();

    for (int base = 0; base < NNODES; base += 4096) {
        int i0 = base + tid * 4;
        int v0 = (i0 + 0 < NNODES) ? g_counts[i0 + 0] : 0;
        int v1 = (i0 + 1 < NNODES) ? g_counts[i0 + 1] : 0;
        int v2 = (i0 + 2 < NNODES) ? g_counts[i0 + 2] : 0;
        int v3 = (i0 + 3 < NNODES) ? g_counts[i0 + 3] : 0;
        int c0 = v0, c1 = c0 + v1, c2 = c1 + v2, c3 = c2 + v3;

        int s = c3;
        #pragma unroll
        for (int off = 1; off < 32; off <<= 1) {
            int n = __shfl_up_sync(0xffffffffu, s, off);
            if (lane >= off) s += n;
        }
        if (lane == 31) wsum[wid] = s;
        __syncthreads();
        if (wid == 0) {
            int t = wsum[lane];
            #pragma unroll
            for (int off = 1; off < 32; off <<= 1) {
                int n = __shfl_up_sync(0xffffffffu, t, off);
                if (lane >= off) t += n;
            }
            wsum[lane] = t;
            if (lane == 31) s_total = t;
        }
        __syncthreads();

        int excl = s_carry + (wid > 0 ? wsum[wid - 1] : 0) + (s - c3);
        if (i0 + 0 < NNODES) { g_offs[i0 + 1] = excl + c0; g_cursor[i0 + 0] = excl; }
        if (i0 + 1 < NNODES) { g_offs[i0 + 2] = excl + c1; g_cursor[i0 + 1] = excl + c0; }
        if (i0 + 2 < NNODES) { g_offs[i0 + 3] = excl + c2; g_cursor[i0 + 2] = excl + c1; }
        if (i0 + 3 < NNODES) { g_offs[i0 + 4] = excl + c3; g_cursor[i0 + 3] = excl + c2; }
        __syncthreads();
        if (tid == 0) s_carry += s_total;
        __syncthreads();
    }
    if (threadIdx.x == 0) g_offs[0] = 0;
}

// scatter: 4 independent edges per thread, packed 8B store
__global__ void scatter_kernel(const int* __restrict__ erows,
                               const int* __restrict__ ecols,
                               const float* __restrict__ evals) {
    int base = blockIdx.x * 1024 + threadIdx.x;
    #pragma unroll
    for (int i = 0; i < 4; i++) {
        int e = base + i * 256;
        if (e < NEDGES) {
            int r = erows[e];
            int pos = atomicAdd(&g_cursor[r], 1);
            g_edge[pos] = make_int2(ecols[e], __float_as_int(evals[e]));
        }
    }
}

// ---------------- GEMM: tf32 mma.sync, x staged via smem ----------------
// block: 256 threads = 8 warps; warp tile 16(M) x 64(N); block tile 128 x 64.
// xs: [128 rows][36] fp32 (K chunked by 32); wsf: B fragments, fragment order.
__global__ __launch_bounds__(256) void gemm_kernel(const float* __restrict__ x,
                                                   const float* __restrict__ w) {
    extern __shared__ float smem[];
    float* xs = smem;                                        // 128 * 36 floats
    unsigned int* wsf = (unsigned int*)(smem + 128 * XS_STRIDE);  // 8192 uints

    int t = threadIdx.x, lane = t & 31, wid = t >> 5;

    // fill W fragments once: i = ((kk*8 + j)*32 + lane)*2 + reg
    for (int i = t; i < 8192; i += 256) {
        int kk = i >> 9;
        int j  = (i >> 6) & 7;
        int ln = (i >> 1) & 31;
        int rg = i & 1;
        int k  = kk * 8 + (ln & 3) + rg * 4;
        int c  = j * 8 + (ln >> 2);
        wsf[i] = f2tf32(w[k * DOUT + c]);
    }

    size_t m0 = (size_t)blockIdx.x * 128 + wid * 16;
    int g   = lane >> 2;     // groupID (row within fragment)
    int tig = lane & 3;      // thread in group

    float4 acc[8] = {};
    const uint2* wsf2 = reinterpret_cast<const uint2*>(wsf);

    int r0 = wid * 16 + g;        // local fragment rows
    int r1 = r0 + 8;

    // x-fill mapping: 1024 float4 per chunk -> 4 per thread
    // i = t + it*256 ; row = i>>3 (0..127), q = i&7 (float4 within 32 floats)
    size_t mrow_base = (size_t)blockIdx.x * 128;

    #pragma unroll 1
    for (int kc = 0; kc < 4; kc++) {          // K chunks of 32
        __syncthreads();
        #pragma unroll
        for (int it = 0; it < 4; it++) {
            int i   = t + it * 256;
            int row = i >> 3;
            int q   = i & 7;
            size_t m = mrow_base + row;
            if (m >= MTOTAL) m = MTOTAL - 1;
            float4 v = *reinterpret_cast<const float4*>(x + m * DIN + kc * 32 + q * 4);
            *reinterpret_cast<float4*>(&xs[row * XS_STRIDE + q * 4]) = v;
        }
        __syncthreads();

        #pragma unroll
        for (int kk8 = 0; kk8 < 4; kk8++) {   // k8 steps within chunk
            int kkg = kc * 4 + kk8;           // absolute k8 index (0..15)
            int klo = kk8 * 8 + tig;
            unsigned int a0 = f2tf32(xs[r0 * XS_STRIDE + klo]);
            unsigned int a1 = f2tf32(xs[r1 * XS_STRIDE + klo]);
            unsigned int a2 = f2tf32(xs[r0 * XS_STRIDE + klo + 4]);
            unsigned int a3 = f2tf32(xs[r1 * XS_STRIDE + klo + 4]);
            #pragma unroll
            for (int j = 0; j < 8; j++) {
                uint2 b = wsf2[(kkg * 8 + j) * 32 + lane];
                mma_tf32(acc[j], a0, a1, a2, a3, b.x, b.y);
            }
        }
    }

    size_t mr0 = m0 + g;
    size_t mr1 = m0 + g + 8;
    bool v0 = mr0 < MTOTAL;
    bool v1 = mr1 < MTOTAL;
    #pragma unroll
    for (int j = 0; j < 8; j++) {
        __half2 h0 = __floats2half2_rn(acc[j].x, acc[j].y);
        __half2 h1 = __floats2half2_rn(acc[j].z, acc[j].w);
        if (v0) *reinterpret_cast<__half2*>(g_preh + mr0 * DOUT + j * 8 + tig * 2) = h0;
        if (v1) *reinterpret_cast<__half2*>(g_preh + mr1 * DOUT + j * 8 + tig * 2) = h1;
    }
}

// ---------------- aggregation: warp per destination row ----------------
__global__ void aggregate_kernel(float* __restrict__ out) {
    int gwarp = (blockIdx.x * blockDim.x + threadIdx.x) >> 5;
    int lane  = threadIdx.x & 31;
    if (gwarp >= NNODES) return;

    int start = g_offs[gwarp];
    int end   = g_offs[gwarp + 1];

    float2 a0 = make_float2(0.f, 0.f), a1 = a0, a2 = a0, a3 = a0;
    const __half2* p2 = reinterpret_cast<const __half2*>(g_preh);
    const size_t bstride = (size_t)NNODES * (DOUT / 2);

    for (int i = start; i < end; i++) {
        int2 e = g_edge[i];
        float v = __int_as_float(e.y);
        size_t base = (size_t)e.x * (DOUT / 2) + lane;
        float2 f;
        f = __half22float2(p2[base]);               a0.x += v * f.x; a0.y += v * f.y;
        f = __half22float2(p2[base +     bstride]); a1.x += v * f.x; a1.y += v * f.y;
        f = __half22float2(p2[base + 2 * bstride]); a2.x += v * f.x; a2.y += v * f.y;
        f = __half22float2(p2[base + 3 * bstride]); a3.x += v * f.x; a3.y += v * f.y;
    }

    float2* o2 = reinterpret_cast<float2*>(out);
    size_t ob = (size_t)gwarp * (DOUT / 2) + lane;
    o2[ob]               = make_float2(fmaxf(a0.x, 0.f), fmaxf(a0.y, 0.f));
    o2[ob +     bstride] = make_float2(fmaxf(a1.x, 0.f), fmaxf(a1.y, 0.f));
    o2[ob + 2 * bstride] = make_float2(fmaxf(a2.x, 0.f), fmaxf(a2.y, 0.f));
    o2[ob + 3 * bstride] = make_float2(fmaxf(a3.x, 0.f), fmaxf(a3.y, 0.f));
}

// ---------------- launch ----------------
extern "C" void kernel_launch(void* const* d_in, const int* in_sizes, int n_in,
                              void* d_out, int out_size) {
    const float* x     = (const float*)d_in[0];
    const float* w     = (const float*)d_in[1];
    const float* evals = (const float*)d_in[2];
    const int*   erows = (const int*)  d_in[3];
    const int*   ecols = (const int*)  d_in[4];
    float* out = (float*)d_out;

    (void)in_sizes; (void)n_in; (void)out_size;

    static bool attr_set = false;
    if (!attr_set) {
        cudaFuncSetAttribute(gemm_kernel,
                             cudaFuncAttributeMaxDynamicSharedMemorySize, GEMM_SMEM);
        attr_set = true;
    }

    zero_counts_kernel<<<(NNODES + 255) / 256, 256>>>();
    hist_kernel<<<NEDGES / 256, 256>>>(erows);
    scan_kernel<<<1, 1024>>>();
    // gemm 4th so the ncu capture slot profiles it
    gemm_kernel<<<(MTOTAL + 127) / 128, 256, GEMM_SMEM>>>(x, w);
    scatter_kernel<<<(NEDGES + 1023) / 1024, 256>>>(erows, ecols, evals);
    aggregate_kernel<<<(NNODES * 32 + 255) / 256, 256>>>(out);
}

// round 7
// speedup vs baseline: 1.5078x; 1.0605x over previous
#include <cuda_runtime.h>
#include <cuda_fp16.h>
#include <cstdint>

#define NB      4
#define NNODES  50000
#define DIN     128
#define DOUT    64
#define NEDGES  800000
#define MTOTAL  (NB * NNODES)

#define XS_STRIDE 36        // bank(row*36 + k) = (4*row + k) % 32  -> conflict-free frags

// ---------------- device scratch ----------------
__device__ __half g_preh[MTOTAL * DOUT];          // [b][node][dout] fp16
__device__ unsigned int g_wf[16 * 8 * 32 * 2];    // W fragments, tf32, fragment order
__device__ int   g_counts[NNODES];
__device__ int   g_offs[NNODES + 1];
__device__ int   g_cursor[NNODES];
__device__ int2  g_edge[NEDGES];                  // {col, float_as_int(val)}

// ---------------- tf32 helpers ----------------
__device__ __forceinline__ unsigned int f2tf32(float f) {
    unsigned int u;
    asm("cvt.rna.tf32.f32 %0, %1;" : "=r"(u) : "f"(f));
    return u;
}
__device__ __forceinline__ void mma_tf32(float4& d,
                                         unsigned int a0, unsigned int a1,
                                         unsigned int a2, unsigned int a3,
                                         unsigned int b0, unsigned int b1) {
    asm("mma.sync.aligned.m16n8k8.row.col.f32.tf32.tf32.f32 "
        "{%0,%1,%2,%3}, {%4,%5,%6,%7}, {%8,%9}, {%0,%1,%2,%3};"
        : "+f"(d.x), "+f"(d.y), "+f"(d.z), "+f"(d.w)
        : "r"(a0), "r"(a1), "r"(a2), "r"(a3), "r"(b0), "r"(b1));
}

// ---------------- CSR build ----------------
__global__ void zero_counts_kernel() {
    int i = blockIdx.x * blockDim.x + threadIdx.x;
    if (i < NNODES) g_counts[i] = 0;
}

__global__ void hist_kernel(const int* __restrict__ erows) {
    int e = blockIdx.x * blockDim.x + threadIdx.x;
    if (e < NEDGES) atomicAdd(&g_counts[erows[e]], 1);
}

// single-block scan: shuffle-based, 4 elems/thread
__global__ void scan_kernel() {
    __shared__ int wsum[32];
    __shared__ int s_carry;
    __shared__ int s_total;
    int tid = threadIdx.x, lane = tid & 31, wid = tid >> 5;
    if (tid == 0) s_carry = 0;
    __syncthreads();

    for (int base = 0; base < NNODES; base += 4096) {
        int i0 = base + tid * 4;
        int v0 = (i0 + 0 < NNODES) ? g_counts[i0 + 0] : 0;
        int v1 = (i0 + 1 < NNODES) ? g_counts[i0 + 1] : 0;
        int v2 = (i0 + 2 < NNODES) ? g_counts[i0 + 2] : 0;
        int v3 = (i0 + 3 < NNODES) ? g_counts[i0 + 3] : 0;
        int c0 = v0, c1 = c0 + v1, c2 = c1 + v2, c3 = c2 + v3;

        int s = c3;
        #pragma unroll
        for (int off = 1; off < 32; off <<= 1) {
            int n = __shfl_up_sync(0xffffffffu, s, off);
            if (lane >= off) s += n;
        }
        if (lane == 31) wsum[wid] = s;
        __syncthreads();
        if (wid == 0) {
            int t = wsum[lane];
            #pragma unroll
            for (int off = 1; off < 32; off <<= 1) {
                int n = __shfl_up_sync(0xffffffffu, t, off);
                if (lane >= off) t += n;
            }
            wsum[lane] = t;
            if (lane == 31) s_total = t;
        }
        __syncthreads();

        int excl = s_carry + (wid > 0 ? wsum[wid - 1] : 0) + (s - c3);
        if (i0 + 0 < NNODES) { g_offs[i0 + 1] = excl + c0; g_cursor[i0 + 0] = excl; }
        if (i0 + 1 < NNODES) { g_offs[i0 + 2] = excl + c1; g_cursor[i0 + 1] = excl + c0; }
        if (i0 + 2 < NNODES) { g_offs[i0 + 3] = excl + c2; g_cursor[i0 + 2] = excl + c1; }
        if (i0 + 3 < NNODES) { g_offs[i0 + 4] = excl + c3; g_cursor[i0 + 3] = excl + c2; }
        __syncthreads();
        if (tid == 0) s_carry += s_total;
        __syncthreads();
    }
    if (threadIdx.x == 0) g_offs[0] = 0;
}

// scatter: 4 independent edges per thread, packed 8B store
__global__ void scatter_kernel(const int* __restrict__ erows,
                               const int* __restrict__ ecols,
                               const float* __restrict__ evals) {
    int base = blockIdx.x * 1024 + threadIdx.x;
    #pragma unroll
    for (int i = 0; i < 4; i++) {
        int e = base + i * 256;
        if (e < NEDGES) {
            int r = erows[e];
            int pos = atomicAdd(&g_cursor[r], 1);
            g_edge[pos] = make_int2(ecols[e], __float_as_int(evals[e]));
        }
    }
}

// ---------------- W fragment prep: tf32, mma B-fragment order ----------------
__global__ void wfrag_kernel(const float* __restrict__ w) {
    int i = blockIdx.x * 256 + threadIdx.x;   // 0..8191
    int kk = i >> 9;
    int j  = (i >> 6) & 7;
    int ln = (i >> 1) & 31;
    int rg = i & 1;
    int k  = kk * 8 + (ln & 3) + rg * 4;
    int c  = j * 8 + (ln >> 2);
    g_wf[i] = f2tf32(w[k * DOUT + c]);
}

// ---------------- GEMM: tf32 mma.sync ----------------
// block: 256 threads = 8 warps; warp tile 32(M) x 64(N); block tile 256 x 64.
// xs: x staged as tf32 bits in smem; B fragments streamed via __ldg (L1-resident).
__global__ __launch_bounds__(256) void gemm_kernel(const float* __restrict__ x) {
    __shared__ unsigned int xs[256 * XS_STRIDE];   // 36.9 KB

    int t = threadIdx.x, lane = t & 31, wid = t >> 5;
    int g   = lane >> 2;     // fragment row within group
    int tig = lane & 3;      // thread-in-group

    size_t mblk = (size_t)blockIdx.x * 256;

    float4 acc[2][8] = {};
    const uint2* wf2 = reinterpret_cast<const uint2*>(g_wf);

    int rA = wid * 32 + g;   // local rows: rA, rA+8 (frag 0); rA+16, rA+24 (frag 1)

    #pragma unroll 1
    for (int kc = 0; kc < 4; kc++) {          // K chunks of 32
        __syncthreads();
        // stage 256 rows x 32 k, converted to tf32: 8 float4 per thread
        #pragma unroll
        for (int it = 0; it < 8; it++) {
            int i   = t + it * 256;
            int row = i >> 3;
            int q   = i & 7;
            size_t m = mblk + row;
            if (m >= MTOTAL) m = MTOTAL - 1;
            float4 v = *reinterpret_cast<const float4*>(x + m * DIN + kc * 32 + q * 4);
            uint4 u = make_uint4(f2tf32(v.x), f2tf32(v.y), f2tf32(v.z), f2tf32(v.w));
            *reinterpret_cast<uint4*>(&xs[row * XS_STRIDE + q * 4]) = u;
        }
        __syncthreads();

        #pragma unroll
        for (int kk8 = 0; kk8 < 4; kk8++) {
            int kkg = kc * 4 + kk8;           // absolute k8 index (0..15)
            int klo = kk8 * 8 + tig;

            unsigned int a00 = xs[(rA     ) * XS_STRIDE + klo];
            unsigned int a01 = xs[(rA +  8) * XS_STRIDE + klo];
            unsigned int a02 = xs[(rA     ) * XS_STRIDE + klo + 4];
            unsigned int a03 = xs[(rA +  8) * XS_STRIDE + klo + 4];
            unsigned int a10 = xs[(rA + 16) * XS_STRIDE + klo];
            unsigned int a11 = xs[(rA + 24) * XS_STRIDE + klo];
            unsigned int a12 = xs[(rA + 16) * XS_STRIDE + klo + 4];
            unsigned int a13 = xs[(rA + 24) * XS_STRIDE + klo + 4];

            #pragma unroll
            for (int j = 0; j < 8; j++) {
                uint2 b = __ldg(&wf2[(kkg * 8 + j) * 32 + lane]);
                mma_tf32(acc[0][j], a00, a01, a02, a03, b.x, b.y);
                mma_tf32(acc[1][j], a10, a11, a12, a13, b.x, b.y);
            }
        }
    }

    #pragma unroll
    for (int f = 0; f < 2; f++) {
        size_t mr0 = mblk + wid * 32 + f * 16 + g;
        size_t mr1 = mr0 + 8;
        bool v0 = mr0 < MTOTAL;
        bool v1 = mr1 < MTOTAL;
        #pragma unroll
        for (int j = 0; j < 8; j++) {
            __half2 h0 = __floats2half2_rn(acc[f][j].x, acc[f][j].y);
            __half2 h1 = __floats2half2_rn(acc[f][j].z, acc[f][j].w);
            if (v0) *reinterpret_cast<__half2*>(g_preh + mr0 * DOUT + j * 8 + tig * 2) = h0;
            if (v1) *reinterpret_cast<__half2*>(g_preh + mr1 * DOUT + j * 8 + tig * 2) = h1;
        }
    }
}

// ---------------- aggregation: warp per destination row, 2-edge unroll ----------------
__global__ void aggregate_kernel(float* __restrict__ out) {
    int gwarp = (blockIdx.x * blockDim.x + threadIdx.x) >> 5;
    int lane  = threadIdx.x & 31;
    if (gwarp >= NNODES) return;

    int start = g_offs[gwarp];
    int end   = g_offs[gwarp + 1];

    float2 a0 = make_float2(0.f, 0.f), a1 = a0, a2 = a0, a3 = a0;
    const __half2* p2 = reinterpret_cast<const __half2*>(g_preh);
    const size_t bstride = (size_t)NNODES * (DOUT / 2);

    int i = start;
    for (; i + 1 < end; i += 2) {
        int2 e0 = g_edge[i];
        int2 e1 = g_edge[i + 1];
        float v0 = __int_as_float(e0.y);
        float v1 = __int_as_float(e1.y);
        size_t b0 = (size_t)e0.x * (DOUT / 2) + lane;
        size_t b1 = (size_t)e1.x * (DOUT / 2) + lane;
        __half2 q00 = p2[b0];
        __half2 q01 = p2[b0 +     bstride];
        __half2 q02 = p2[b0 + 2 * bstride];
        __half2 q03 = p2[b0 + 3 * bstride];
        __half2 q10 = p2[b1];
        __half2 q11 = p2[b1 +     bstride];
        __half2 q12 = p2[b1 + 2 * bstride];
        __half2 q13 = p2[b1 + 3 * bstride];
        float2 f;
        f = __half22float2(q00); a0.x += v0 * f.x; a0.y += v0 * f.y;
        f = __half22float2(q01); a1.x += v0 * f.x; a1.y += v0 * f.y;
        f = __half22float2(q02); a2.x += v0 * f.x; a2.y += v0 * f.y;
        f = __half22float2(q03); a3.x += v0 * f.x; a3.y += v0 * f.y;
        f = __half22float2(q10); a0.x += v1 * f.x; a0.y += v1 * f.y;
        f = __half22float2(q11); a1.x += v1 * f.x; a1.y += v1 * f.y;
        f = __half22float2(q12); a2.x += v1 * f.x; a2.y += v1 * f.y;
        f = __half22float2(q13); a3.x += v1 * f.x; a3.y += v1 * f.y;
    }
    if (i < end) {
        int2 e0 = g_edge[i];
        float v0 = __int_as_float(e0.y);
        size_t b0 = (size_t)e0.x * (DOUT / 2) + lane;
        float2 f;
        f = __half22float2(p2[b0]);               a0.x += v0 * f.x; a0.y += v0 * f.y;
        f = __half22float2(p2[b0 +     bstride]); a1.x += v0 * f.x; a1.y += v0 * f.y;
        f = __half22float2(p2[b0 + 2 * bstride]); a2.x += v0 * f.x; a2.y += v0 * f.y;
        f = __half22float2(p2[b0 + 3 * bstride]); a3.x += v0 * f.x; a3.y += v0 * f.y;
    }

    float2* o2 = reinterpret_cast<float2*>(out);
    size_t ob = (size_t)gwarp * (DOUT / 2) + lane;
    o2[ob]               = make_float2(fmaxf(a0.x, 0.f), fmaxf(a0.y, 0.f));
    o2[ob +     bstride] = make_float2(fmaxf(a1.x, 0.f), fmaxf(a1.y, 0.f));
    o2[ob + 2 * bstride] = make_float2(fmaxf(a2.x, 0.f), fmaxf(a2.y, 0.f));
    o2[ob + 3 * bstride] = make_float2(fmaxf(a3.x, 0.f), fmaxf(a3.y, 0.f));
}

// ---------------- launch ----------------
extern "C" void kernel_launch(void* const* d_in, const int* in_sizes, int n_in,
                              void* d_out, int out_size) {
    const float* x     = (const float*)d_in[0];
    const float* w     = (const float*)d_in[1];
    const float* evals = (const float*)d_in[2];
    const int*   erows = (const int*)  d_in[3];
    const int*   ecols = (const int*)  d_in[4];
    float* out = (float*)d_out;

    (void)in_sizes; (void)n_in; (void)out_size;

    zero_counts_kernel<<<(NNODES + 255) / 256, 256>>>();
    hist_kernel<<<NEDGES / 256, 256>>>(erows);
    wfrag_kernel<<<32, 256>>>(w);
    scan_kernel<<<1, 1024>>>();
    // gemm 5th; keep in capture window for ncu
    gemm_kernel<<<(MTOTAL + 255) / 256, 256>>>(x);
    scatter_kernel<<<(NEDGES + 1023) / 1024, 256>>>(erows, ecols, evals);
    aggregate_kernel<<<(NNODES * 32 + 255) / 256, 256>>>(out);
}

// round 8
// speedup vs baseline: 1.8467x; 1.2248x over previous
#include <cuda_runtime.h>
#include <cuda_fp16.h>
#include <cstdint>

#define NB      4
#define NNODES  50000
#define DIN     128
#define DOUT    64
#define NEDGES  800000
#define MTOTAL  (NB * NNODES)

#define XS_STRIDE 36
#define SCAN_TILE 4096
#define NSCAN_BLOCKS ((NNODES + SCAN_TILE - 1) / SCAN_TILE)   // 13

// ---------------- device scratch ----------------
__device__ __half g_preh[MTOTAL * DOUT];          // [b][node][dout] fp16
__device__ unsigned int g_wf[16 * 8 * 32 * 2];    // W fragments, tf32, fragment order
__device__ int   g_counts[NNODES];
__device__ int   g_offs[NNODES + 1];
__device__ int   g_cursor[NNODES];
__device__ int   g_bsum[NSCAN_BLOCKS];
__device__ int2  g_edge[NEDGES];                  // {col, float_as_int(val)}

// ---------------- tf32 helpers ----------------
__device__ __forceinline__ unsigned int f2tf32(float f) {
    unsigned int u;
    asm("cvt.rna.tf32.f32 %0, %1;" : "=r"(u) : "f"(f));
    return u;
}
__device__ __forceinline__ void mma_tf32(float4& d,
                                         unsigned int a0, unsigned int a1,
                                         unsigned int a2, unsigned int a3,
                                         unsigned int b0, unsigned int b1) {
    asm("mma.sync.aligned.m16n8k8.row.col.f32.tf32.tf32.f32 "
        "{%0,%1,%2,%3}, {%4,%5,%6,%7}, {%8,%9}, {%0,%1,%2,%3};"
        : "+f"(d.x), "+f"(d.y), "+f"(d.z), "+f"(d.w)
        : "r"(a0), "r"(a1), "r"(a2), "r"(a3), "r"(b0), "r"(b1));
}

// ---------------- CSR build ----------------
__global__ void hist_kernel(const int* __restrict__ erows) {
    int e = blockIdx.x * blockDim.x + threadIdx.x;
    if (e < NEDGES) atomicAdd(&g_counts[erows[e]], 1);
}

// phase 1: per-block local scan (4096 elems / block), write local values + block sum
__global__ void scan1_kernel() {
    __shared__ int wsum[32];
    int tid = threadIdx.x, lane = tid & 31, wid = tid >> 5;
    int base = blockIdx.x * SCAN_TILE;

    int i0 = base + tid * 4;
    int v0 = (i0 + 0 < NNODES) ? g_counts[i0 + 0] : 0;
    int v1 = (i0 + 1 < NNODES) ? g_counts[i0 + 1] : 0;
    int v2 = (i0 + 2 < NNODES) ? g_counts[i0 + 2] : 0;
    int v3 = (i0 + 3 < NNODES) ? g_counts[i0 + 3] : 0;
    int c0 = v0, c1 = c0 + v1, c2 = c1 + v2, c3 = c2 + v3;

    int s = c3;
    #pragma unroll
    for (int off = 1; off < 32; off <<= 1) {
        int n = __shfl_up_sync(0xffffffffu, s, off);
        if (lane >= off) s += n;
    }
    if (lane == 31) wsum[wid] = s;
    __syncthreads();
    if (wid == 0) {
        int t = wsum[lane];
        #pragma unroll
        for (int off = 1; off < 32; off <<= 1) {
            int n = __shfl_up_sync(0xffffffffu, t, off);
            if (lane >= off) t += n;
        }
        wsum[lane] = t;
        if (lane == 31) g_bsum[blockIdx.x] = t;   // block total
    }
    __syncthreads();

    int excl = (wid > 0 ? wsum[wid - 1] : 0) + (s - c3);   // local exclusive
    if (i0 + 0 < NNODES) { g_offs[i0 + 1] = excl + c0; g_cursor[i0 + 0] = excl; }
    if (i0 + 1 < NNODES) { g_offs[i0 + 2] = excl + c1; g_cursor[i0 + 1] = excl + c0; }
    if (i0 + 2 < NNODES) { g_offs[i0 + 3] = excl + c2; g_cursor[i0 + 2] = excl + c1; }
    if (i0 + 3 < NNODES) { g_offs[i0 + 4] = excl + c3; g_cursor[i0 + 3] = excl + c2; }
    if (blockIdx.x == 0 && tid == 0) g_offs[0] = 0;
}

// phase 2: one warp scans the block sums (exclusive)
__global__ void scan2_kernel() {
    int lane = threadIdx.x;
    int v = (lane < NSCAN_BLOCKS) ? g_bsum[lane] : 0;
    int s = v;
    #pragma unroll
    for (int off = 1; off < 32; off <<= 1) {
        int n = __shfl_up_sync(0xffffffffu, s, off);
        if (lane >= off) s += n;
    }
    if (lane < NSCAN_BLOCKS) g_bsum[lane] = s - v;   // exclusive
}

// phase 3: add block offsets
__global__ void scan3_kernel() {
    int boff = g_bsum[blockIdx.x];
    if (boff == 0) return;           // block 0 and any empty prefix: nothing to add
    int tid = threadIdx.x;
    int base = blockIdx.x * SCAN_TILE;
    #pragma unroll
    for (int q = 0; q < 4; q++) {
        int i = base + tid * 4 + q;
        if (i < NNODES) {
            g_offs[i + 1] += boff;
            g_cursor[i]   += boff;
        }
    }
}

// scatter: 4 independent edges per thread, packed 8B store
__global__ void scatter_kernel(const int* __restrict__ erows,
                               const int* __restrict__ ecols,
                               const float* __restrict__ evals) {
    int base = blockIdx.x * 1024 + threadIdx.x;
    #pragma unroll
    for (int i = 0; i < 4; i++) {
        int e = base + i * 256;
        if (e < NEDGES) {
            int r = erows[e];
            int pos = atomicAdd(&g_cursor[r], 1);
            g_edge[pos] = make_int2(ecols[e], __float_as_int(evals[e]));
        }
    }
}

// ---------------- W fragment prep: tf32, mma B-fragment order ----------------
__global__ void wfrag_kernel(const float* __restrict__ w) {
    int i = blockIdx.x * 256 + threadIdx.x;   // 0..8191
    int kk = i >> 9;
    int j  = (i >> 6) & 7;
    int ln = (i >> 1) & 31;
    int rg = i & 1;
    int k  = kk * 8 + (ln & 3) + rg * 4;
    int c  = j * 8 + (ln >> 2);
    g_wf[i] = f2tf32(w[k * DOUT + c]);
}

// ---------------- GEMM: tf32 mma.sync (unchanged from R7) ----------------
__global__ __launch_bounds__(256) void gemm_kernel(const float* __restrict__ x) {
    __shared__ unsigned int xs[256 * XS_STRIDE];

    int t = threadIdx.x, lane = t & 31, wid = t >> 5;
    int g   = lane >> 2;
    int tig = lane & 3;

    size_t mblk = (size_t)blockIdx.x * 256;

    float4 acc[2][8] = {};
    const uint2* wf2 = reinterpret_cast<const uint2*>(g_wf);

    int rA = wid * 32 + g;

    #pragma unroll 1
    for (int kc = 0; kc < 4; kc++) {
        __syncthreads();
        #pragma unroll
        for (int it = 0; it < 8; it++) {
            int i   = t + it * 256;
            int row = i >> 3;
            int q   = i & 7;
            size_t m = mblk + row;
            if (m >= MTOTAL) m = MTOTAL - 1;
            float4 v = *reinterpret_cast<const float4*>(x + m * DIN + kc * 32 + q * 4);
            uint4 u = make_uint4(f2tf32(v.x), f2tf32(v.y), f2tf32(v.z), f2tf32(v.w));
            *reinterpret_cast<uint4*>(&xs[row * XS_STRIDE + q * 4]) = u;
        }
        __syncthreads();

        #pragma unroll
        for (int kk8 = 0; kk8 < 4; kk8++) {
            int kkg = kc * 4 + kk8;
            int klo = kk8 * 8 + tig;

            unsigned int a00 = xs[(rA     ) * XS_STRIDE + klo];
            unsigned int a01 = xs[(rA +  8) * XS_STRIDE + klo];
            unsigned int a02 = xs[(rA     ) * XS_STRIDE + klo + 4];
            unsigned int a03 = xs[(rA +  8) * XS_STRIDE + klo + 4];
            unsigned int a10 = xs[(rA + 16) * XS_STRIDE + klo];
            unsigned int a11 = xs[(rA + 24) * XS_STRIDE + klo];
            unsigned int a12 = xs[(rA + 16) * XS_STRIDE + klo + 4];
            unsigned int a13 = xs[(rA + 24) * XS_STRIDE + klo + 4];

            #pragma unroll
            for (int j = 0; j < 8; j++) {
                uint2 b = __ldg(&wf2[(kkg * 8 + j) * 32 + lane]);
                mma_tf32(acc[0][j], a00, a01, a02, a03, b.x, b.y);
                mma_tf32(acc[1][j], a10, a11, a12, a13, b.x, b.y);
            }
        }
    }

    #pragma unroll
    for (int f = 0; f < 2; f++) {
        size_t mr0 = mblk + wid * 32 + f * 16 + g;
        size_t mr1 = mr0 + 8;
        bool v0 = mr0 < MTOTAL;
        bool v1 = mr1 < MTOTAL;
        #pragma unroll
        for (int j = 0; j < 8; j++) {
            __half2 h0 = __floats2half2_rn(acc[f][j].x, acc[f][j].y);
            __half2 h1 = __floats2half2_rn(acc[f][j].z, acc[f][j].w);
            if (v0) *reinterpret_cast<__half2*>(g_preh + mr0 * DOUT + j * 8 + tig * 2) = h0;
            if (v1) *reinterpret_cast<__half2*>(g_preh + mr1 * DOUT + j * 8 + tig * 2) = h1;
        }
    }
}

// ---------------- aggregation (unchanged from R7) ----------------
__global__ void aggregate_kernel(float* __restrict__ out) {
    int gwarp = (blockIdx.x * blockDim.x + threadIdx.x) >> 5;
    int lane  = threadIdx.x & 31;
    if (gwarp >= NNODES) return;

    int start = g_offs[gwarp];
    int end   = g_offs[gwarp + 1];

    float2 a0 = make_float2(0.f, 0.f), a1 = a0, a2 = a0, a3 = a0;
    const __half2* p2 = reinterpret_cast<const __half2*>(g_preh);
    const size_t bstride = (size_t)NNODES * (DOUT / 2);

    int i = start;
    for (; i + 1 < end; i += 2) {
        int2 e0 = g_edge[i];
        int2 e1 = g_edge[i + 1];
        float v0 = __int_as_float(e0.y);
        float v1 = __int_as_float(e1.y);
        size_t b0 = (size_t)e0.x * (DOUT / 2) + lane;
        size_t b1 = (size_t)e1.x * (DOUT / 2) + lane;
        __half2 q00 = p2[b0];
        __half2 q01 = p2[b0 +     bstride];
        __half2 q02 = p2[b0 + 2 * bstride];
        __half2 q03 = p2[b0 + 3 * bstride];
        __half2 q10 = p2[b1];
        __half2 q11 = p2[b1 +     bstride];
        __half2 q12 = p2[b1 + 2 * bstride];
        __half2 q13 = p2[b1 + 3 * bstride];
        float2 f;
        f = __half22float2(q00); a0.x += v0 * f.x; a0.y += v0 * f.y;
        f = __half22float2(q01); a1.x += v0 * f.x; a1.y += v0 * f.y;
        f = __half22float2(q02); a2.x += v0 * f.x; a2.y += v0 * f.y;
        f = __half22float2(q03); a3.x += v0 * f.x; a3.y += v0 * f.y;
        f = __half22float2(q10); a0.x += v1 * f.x; a0.y += v1 * f.y;
        f = __half22float2(q11); a1.x += v1 * f.x; a1.y += v1 * f.y;
        f = __half22float2(q12); a2.x += v1 * f.x; a2.y += v1 * f.y;
        f = __half22float2(q13); a3.x += v1 * f.x; a3.y += v1 * f.y;
    }
    if (i < end) {
        int2 e0 = g_edge[i];
        float v0 = __int_as_float(e0.y);
        size_t b0 = (size_t)e0.x * (DOUT / 2) + lane;
        float2 f;
        f = __half22float2(p2[b0]);               a0.x += v0 * f.x; a0.y += v0 * f.y;
        f = __half22float2(p2[b0 +     bstride]); a1.x += v0 * f.x; a1.y += v0 * f.y;
        f = __half22float2(p2[b0 + 2 * bstride]); a2.x += v0 * f.x; a2.y += v0 * f.y;
        f = __half22float2(p2[b0 + 3 * bstride]); a3.x += v0 * f.x; a3.y += v0 * f.y;
    }

    float2* o2 = reinterpret_cast<float2*>(out);
    size_t ob = (size_t)gwarp * (DOUT / 2) + lane;
    o2[ob]               = make_float2(fmaxf(a0.x, 0.f), fmaxf(a0.y, 0.f));
    o2[ob +     bstride] = make_float2(fmaxf(a1.x, 0.f), fmaxf(a1.y, 0.f));
    o2[ob + 2 * bstride] = make_float2(fmaxf(a2.x, 0.f), fmaxf(a2.y, 0.f));
    o2[ob + 3 * bstride] = make_float2(fmaxf(a3.x, 0.f), fmaxf(a3.y, 0.f));
}

// ---------------- launch ----------------
extern "C" void kernel_launch(void* const* d_in, const int* in_sizes, int n_in,
                              void* d_out, int out_size) {
    const float* x     = (const float*)d_in[0];
    const float* w     = (const float*)d_in[1];
    const float* evals = (const float*)d_in[2];
    const int*   erows = (const int*)  d_in[3];
    const int*   ecols = (const int*)  d_in[4];
    float* out = (float*)d_out;

    (void)in_sizes; (void)n_in; (void)out_size;

    // zero counts via capturable memset node (replaces zero kernel)
    void* counts_ptr = nullptr;
    cudaGetSymbolAddress(&counts_ptr, g_counts);
    cudaMemsetAsync(counts_ptr, 0, NNODES * sizeof(int), 0);

    // kernel launch index 3 (0-based) gets profiled by the ncu slot -> gemm
    hist_kernel<<<NEDGES / 256, 256>>>(erows);        // idx 0
    wfrag_kernel<<<32, 256>>>(w);                     // idx 1
    scan1_kernel<<<NSCAN_BLOCKS, 1024>>>();           // idx 2
    gemm_kernel<<<(MTOTAL + 255) / 256, 256>>>(x);    // idx 3  <- profiled
    scan2_kernel<<<1, 32>>>();                        // idx 4
    scan3_kernel<<<NSCAN_BLOCKS, 1024>>>();           // idx 5
    scatter_kernel<<<(NEDGES + 1023) / 1024, 256>>>(erows, ecols, evals);
    aggregate_kernel<<<(NNODES * 32 + 255) / 256, 256>>>(out);
}